// round 17
// baseline (speedup 1.0000x reference)
#include <cuda_runtime.h>
#include <cuda_bf16.h>
#include <cstdint>

#define HID 256
#define NHEAD 4
#define MAXN 20000
#define MAXE 320000
#define SCAN_T 1024

// ---------------- scratch (device globals; no allocation allowed) ----------------
__device__ uint32_t       g_h   [(size_t)MAXN * HID];      // ln1 out (tf32) for skip GEMM
__device__ uint32_t       g_h16 [(size_t)MAXN * HID / 2];  // ln1/ln2 out (bf16 pairs)
__device__ __nv_bfloat16  g_q   [(size_t)MAXN * HID];
__device__ __nv_bfloat16  g_k   [(size_t)MAXN * HID];
__device__ __nv_bfloat16  g_v   [(size_t)MAXN * HID];
__device__ float          g_skip[(size_t)MAXN * HID];
__device__ float          g_agg [(size_t)MAXN * HID];
__device__ __nv_bfloat16  g_mid [(size_t)MAXN * 2 * HID];
__device__ float          g_den [MAXN * NHEAD];
__device__ int            g_is64;
// CSR scratch
__device__ int g_count [MAXN];
__device__ int g_rowptr[MAXN + 1];
__device__ int g_wpos  [MAXN];
__device__ int g_csrsrc[MAXE];
// converted weights
__device__ uint32_t g_wt  [4][HID * HID];
__device__ uint32_t g_w1t [HID * 2 * HID];
__device__ uint32_t g_w2t [2 * HID * HID];

// ---------------- helpers ----------------
__device__ __forceinline__ int load_idx(const int* __restrict__ ei, int pos, int is64) {
    return is64 ? ei[(size_t)pos * 2] : ei[pos];
}
__device__ __forceinline__ void red_add_v2(float* p, float a, float b) {
    asm volatile("red.global.add.v2.f32 [%0], {%1,%2};"
                 :: "l"(p), "f"(a), "f"(b) : "memory");
}
__device__ __forceinline__ float gelu_exact(float v) {
    return 0.5f * v * (1.0f + erff(v * 0.7071067811865476f));
}
__device__ __forceinline__ uint32_t f2tf(float x) {
    uint32_t r; asm("cvt.rna.tf32.f32 %0, %1;" : "=r"(r) : "f"(x)); return r;
}
__device__ __forceinline__ uint32_t pack_bf2(float lo, float hi) {
    uint32_t l = __bfloat16_as_ushort(__float2bfloat16_rn(lo));
    uint32_t h = __bfloat16_as_ushort(__float2bfloat16_rn(hi));
    return l | (h << 16);
}
__device__ __forceinline__ void mma_tf32(float* c, uint32_t a0, uint32_t a1, uint32_t a2,
                                         uint32_t a3, uint32_t b0, uint32_t b1) {
    asm volatile("mma.sync.aligned.m16n8k8.row.col.f32.tf32.tf32.f32 "
                 "{%0,%1,%2,%3}, {%4,%5,%6,%7}, {%8,%9}, {%0,%1,%2,%3};"
                 : "+f"(c[0]), "+f"(c[1]), "+f"(c[2]), "+f"(c[3])
                 : "r"(a0), "r"(a1), "r"(a2), "r"(a3), "r"(b0), "r"(b1));
}
__device__ __forceinline__ void mma_bf16(float* c, uint32_t a0, uint32_t a1, uint32_t a2,
                                         uint32_t a3, uint32_t b0, uint32_t b1) {
    asm volatile("mma.sync.aligned.m16n8k16.row.col.f32.bf16.bf16.f32 "
                 "{%0,%1,%2,%3}, {%4,%5,%6,%7}, {%8,%9}, {%0,%1,%2,%3};"
                 : "+f"(c[0]), "+f"(c[1]), "+f"(c[2]), "+f"(c[3])
                 : "r"(a0), "r"(a1), "r"(a2), "r"(a3), "r"(b0), "r"(b1));
}

// ---------------- dtype detection (1 warp, 2 rounds = 64 samples) ----------------
__global__ void detect_kernel(const int* __restrict__ ei, int E) {
    int lane = threadIdx.x;
    int nz = ei[2 * lane + 1];
    if (64 <= E) nz |= ei[2 * (lane + 32) + 1];
    #pragma unroll
    for (int o = 16; o > 0; o >>= 1) nz |= __shfl_xor_sync(0xffffffffu, nz, o);
    if (lane == 0) g_is64 = (nz == 0) ? 1 : 0;
}

// ---------------- weight conversion: wskip -> tf32 ----------------
__global__ void cvt_wskip_kernel(const float* __restrict__ src, uint32_t* __restrict__ dst) {
    int i = (blockIdx.x * blockDim.x + threadIdx.x) * 4;
    float4 v = *(const float4*)(src + i);
    *(uint4*)(dst + i) = make_uint4(f2tf(v.x), f2tf(v.y), f2tf(v.z), f2tf(v.w));
}

// ---------------- weight conversion: q/k/v/w1/w2 -> bf16 k-pair packed ----------------
struct WPack { const float* src[5]; uint32_t* dst[5]; };
__global__ void cvt_bf16pack_kernel(WPack wp) {
    int i4 = (blockIdx.x * blockDim.x + threadIdx.x) * 4;   // 229376 words total
    int seg, base, N;
    if (i4 < 98304)       { seg = i4 >> 15; base = seg << 15; N = 256; }
    else if (i4 < 163840) { seg = 3; base = 98304;  N = 512; }
    else                  { seg = 4; base = 163840; N = 256; }
    int off = i4 - base;
    int kw = off / N, n = off % N;
    const float* s = wp.src[seg];
    float4 a = *(const float4*)(s + (size_t)(2 * kw) * N + n);
    float4 b = *(const float4*)(s + (size_t)(2 * kw + 1) * N + n);
    uint4 o;
    o.x = pack_bf2(a.x, b.x);
    o.y = pack_bf2(a.y, b.y);
    o.z = pack_bf2(a.z, b.z);
    o.w = pack_bf2(a.w, b.w);
    *(uint4*)(wp.dst[seg] + off) = o;
}

// ---------------- init: zero degree counters ----------------
__global__ void init_kernel(int* __restrict__ count, int n) {
    int i = blockIdx.x * blockDim.x + threadIdx.x;
    if (i < n) count[i] = 0;
}

// ---------------- CSR build ----------------
__global__ void count_kernel(const int* __restrict__ ei, int* __restrict__ count, int E) {
    int e = blockIdx.x * blockDim.x + threadIdx.x;
    if (e >= E) return;
    int dst = load_idx(ei, E + e, g_is64);
    atomicAdd(&count[dst], 1);
}
__global__ void scan_kernel(const int* __restrict__ count, int* __restrict__ rowptr,
                            int* __restrict__ wpos, int n) {
    __shared__ int part[SCAN_T];
    int t = threadIdx.x;
    int per = (n + SCAN_T - 1) / SCAN_T;
    int start = t * per;
    int end = min(start + per, n);
    int s = 0;
    for (int i = start; i < end; i++) s += count[i];
    part[t] = s;
    __syncthreads();
    for (int off = 1; off < SCAN_T; off <<= 1) {
        int vv = (t >= off) ? part[t - off] : 0;
        __syncthreads();
        part[t] += vv;
        __syncthreads();
    }
    int prefix = (t == 0) ? 0 : part[t - 1];
    for (int i = start; i < end; i++) {
        rowptr[i] = prefix;
        wpos[i]   = prefix;
        prefix += count[i];
    }
    if (t == SCAN_T - 1) rowptr[n] = part[SCAN_T - 1];
}
__global__ void scatter_kernel(const int* __restrict__ ei, int* __restrict__ wpos,
                               int* __restrict__ csrsrc, int E) {
    int e = blockIdx.x * blockDim.x + threadIdx.x;
    if (e >= E) return;
    int is64 = g_is64;
    int src = load_idx(ei, e, is64);
    int dst = load_idx(ei, E + e, is64);
    int pos = atomicAdd(&wpos[dst], 1);
    csrsrc[pos] = src;
}

// ---------------- LayerNorm -> tf32 + bf16-pair ----------------
__global__ void ln_kernel(const float* __restrict__ x, const float* __restrict__ w,
                          const float* __restrict__ b, uint32_t* __restrict__ out32,
                          uint32_t* __restrict__ out16, int n) {
    int row = (blockIdx.x * blockDim.x + threadIdx.x) >> 5;
    if (row >= n) return;
    int lane = threadIdx.x & 31;
    const float4* xp = (const float4*)(x + (size_t)row * HID);
    float4 v0 = xp[lane * 2], v1 = xp[lane * 2 + 1];
    float s  = v0.x + v0.y + v0.z + v0.w + v1.x + v1.y + v1.z + v1.w;
    float sq = v0.x*v0.x + v0.y*v0.y + v0.z*v0.z + v0.w*v0.w
             + v1.x*v1.x + v1.y*v1.y + v1.z*v1.z + v1.w*v1.w;
    #pragma unroll
    for (int o = 16; o > 0; o >>= 1) {
        s  += __shfl_xor_sync(0xffffffffu, s,  o);
        sq += __shfl_xor_sync(0xffffffffu, sq, o);
    }
    float mean = s * (1.0f / HID);
    float var  = sq * (1.0f / HID) - mean * mean;
    float rstd = rsqrtf(var + 1e-5f);
    const float4* wp = (const float4*)w;
    const float4* bp = (const float4*)b;
    uint4* op = (uint4*)(out32 + (size_t)row * HID);
    float o8[8];
    #pragma unroll
    for (int i = 0; i < 2; i++) {
        float4 xv = (i == 0) ? v0 : v1;
        float4 wv = wp[lane * 2 + i], bv = bp[lane * 2 + i];
        o8[4*i+0] = (xv.x - mean) * rstd * wv.x + bv.x;
        o8[4*i+1] = (xv.y - mean) * rstd * wv.y + bv.y;
        o8[4*i+2] = (xv.z - mean) * rstd * wv.z + bv.z;
        o8[4*i+3] = (xv.w - mean) * rstd * wv.w + bv.w;
        op[lane * 2 + i] = make_uint4(f2tf(o8[4*i]), f2tf(o8[4*i+1]),
                                      f2tf(o8[4*i+2]), f2tf(o8[4*i+3]));
    }
    uint4 ob = make_uint4(pack_bf2(o8[0], o8[1]), pack_bf2(o8[2], o8[3]),
                          pack_bf2(o8[4], o8[5]), pack_bf2(o8[6], o8[7]));
    ((uint4*)(out16 + (size_t)row * (HID / 2)))[lane] = ob;
}

// ---------------- add_ln over row range [row0, row0+nrows) ----------------
__global__ void add_ln_kernel(const float* __restrict__ x, const float* __restrict__ skip,
                              const float* __restrict__ agg, const float* __restrict__ den,
                              const float* __restrict__ w, const float* __restrict__ b,
                              const float* __restrict__ b2,
                              float* __restrict__ dout, uint32_t* __restrict__ hout16,
                              int row0, int nrows) {
    int r = (blockIdx.x * blockDim.x + threadIdx.x) >> 5;
    if (r >= nrows) return;
    int row = row0 + r;
    int lane = threadIdx.x & 31;
    int h = lane >> 3;
    float d = den[row * NHEAD + h];
    float rden = (d > 0.0f) ? (1.0f / d) : 0.0f;
    const float4* xp = (const float4*)(x    + (size_t)row * HID);
    const float4* sp = (const float4*)(skip + (size_t)row * HID);
    const float4* ap = (const float4*)(agg  + (size_t)row * HID);
    float4 a0 = xp[lane * 2], a1 = xp[lane * 2 + 1];
    float4 c0 = sp[lane * 2], c1 = sp[lane * 2 + 1];
    float4 g0 = ap[lane * 2], g1 = ap[lane * 2 + 1];
    float4 v0 = make_float4(a0.x + c0.x + g0.x * rden, a0.y + c0.y + g0.y * rden,
                            a0.z + c0.z + g0.z * rden, a0.w + c0.w + g0.w * rden);
    float4 v1 = make_float4(a1.x + c1.x + g1.x * rden, a1.y + c1.y + g1.y * rden,
                            a1.z + c1.z + g1.z * rden, a1.w + c1.w + g1.w * rden);
    const float4* b2p = (const float4*)b2;
    float4 t0 = b2p[lane * 2], t1 = b2p[lane * 2 + 1];
    float4* dp = (float4*)(dout + (size_t)row * HID);
    dp[lane * 2]     = make_float4(v0.x + t0.x, v0.y + t0.y, v0.z + t0.z, v0.w + t0.w);
    dp[lane * 2 + 1] = make_float4(v1.x + t1.x, v1.y + t1.y, v1.z + t1.z, v1.w + t1.w);
    float s  = v0.x + v0.y + v0.z + v0.w + v1.x + v1.y + v1.z + v1.w;
    float sq = v0.x*v0.x + v0.y*v0.y + v0.z*v0.z + v0.w*v0.w
             + v1.x*v1.x + v1.y*v1.y + v1.z*v1.z + v1.w*v1.w;
    #pragma unroll
    for (int o = 16; o > 0; o >>= 1) {
        s  += __shfl_xor_sync(0xffffffffu, s,  o);
        sq += __shfl_xor_sync(0xffffffffu, sq, o);
    }
    float mean = s * (1.0f / HID);
    float var  = sq * (1.0f / HID) - mean * mean;
    float rstd = rsqrtf(var + 1e-5f);
    const float4* wp = (const float4*)w;
    const float4* bp = (const float4*)b;
    float o8[8];
    #pragma unroll
    for (int i = 0; i < 2; i++) {
        float4 xv = (i == 0) ? v0 : v1;
        float4 wv = wp[lane * 2 + i], bv = bp[lane * 2 + i];
        o8[4*i+0] = (xv.x - mean) * rstd * wv.x + bv.x;
        o8[4*i+1] = (xv.y - mean) * rstd * wv.y + bv.y;
        o8[4*i+2] = (xv.z - mean) * rstd * wv.z + bv.z;
        o8[4*i+3] = (xv.w - mean) * rstd * wv.w + bv.w;
    }
    uint4 ob = make_uint4(pack_bf2(o8[0], o8[1]), pack_bf2(o8[2], o8[3]),
                          pack_bf2(o8[4], o8[5]), pack_bf2(o8[6], o8[7]));
    ((uint4*)(hout16 + (size_t)row * (HID / 2)))[lane] = ob;
}

struct GemmPtrs { const uint32_t* W[4]; const float* bias[4]; void* out[4]; };

// ---------------- TF32 GEMM (skip only, EPI 0) ----------------
template<int EPI>
__global__ __launch_bounds__(256)
void gemm_tf32(const uint32_t* __restrict__ A, GemmPtrs p,
               int M, int N, int K, int Kloop) {
    __shared__ __align__(16) uint32_t As[2][2048];
    __shared__ __align__(16) uint32_t Bs[2][2048];
    const uint32_t* __restrict__ W    = p.W[blockIdx.z];
    const float* __restrict__    bias = p.bias[blockIdx.z];
    const int t = threadIdx.x;
    const int lane = t & 31, wid = t >> 5;
    const int wm = wid & 1, wn = wid >> 1;
    const int mBase = blockIdx.x * 128;
    const int nBase = blockIdx.y * 128;
    const int lr = lane >> 2, lc = lane & 3;
    const int rA = t >> 2,  cA = (t & 3) * 4;
    const int rB = t >> 5,  cB = (t & 31) * 4;
    const int laneA = lane ^ ((lane >> 3) & 3);
    int offA[4], offB[4];
    {
        int mt = rA >> 4, s1 = (rA >> 3) & 1, lr0 = rA & 7;
        int ks = cA >> 3, s2 = (cA >> 2) & 1;
        int e  = s1 * 2 + s2;
        int blk = (mt * 2 + ks) * 32;
        #pragma unroll
        for (int j = 0; j < 4; j++) {
            int la = 4 * lr0 + j;
            la ^= (la >> 3) & 3;
            offA[j] = (blk + la) * 4 + e;
        }
        int sB = (rB >> 2) & 1, lcb = rB & 3;
        #pragma unroll
        for (int j = 0; j < 4; j++) {
            int nn = cB + j;
            int nt = nn >> 3, lrb = nn & 7;
            int lb = (4 * lrb + lcb) ^ nt;
            offB[j] = (nt * 2 * 32 + lb) * 2 + sB;
        }
    }
    float acc[4][4][4];
    #pragma unroll
    for (int i = 0; i < 4; i++)
        #pragma unroll
        for (int j = 0; j < 4; j++)
            #pragma unroll
            for (int r = 0; r < 4; r++) acc[i][j][r] = 0.0f;
    const int NK = Kloop >> 4;
    uint4 pa0, pa1, pb0, pb1;
    const uint4 z4 = make_uint4(0u, 0u, 0u, 0u);
    {
        int gr0 = mBase + rA, gr1 = gr0 + 64;
        pa0 = (gr0 < M) ? *(const uint4*)(A + (size_t)gr0 * K + cA) : z4;
        pa1 = (gr1 < M) ? *(const uint4*)(A + (size_t)gr1 * K + cA) : z4;
        pb0 = *(const uint4*)(W + (size_t)rB       * N + nBase + cB);
        pb1 = *(const uint4*)(W + (size_t)(rB + 8) * N + nBase + cB);
        uint32_t* sa = As[0];
        sa[offA[0]] = pa0.x; sa[offA[1]] = pa0.y; sa[offA[2]] = pa0.z; sa[offA[3]] = pa0.w;
        sa += 1024;
        sa[offA[0]] = pa1.x; sa[offA[1]] = pa1.y; sa[offA[2]] = pa1.z; sa[offA[3]] = pa1.w;
        uint32_t* sb = Bs[0];
        sb[offB[0]] = pb0.x; sb[offB[1]] = pb0.y; sb[offB[2]] = pb0.z; sb[offB[3]] = pb0.w;
        sb += 64;
        sb[offB[0]] = pb1.x; sb[offB[1]] = pb1.y; sb[offB[2]] = pb1.z; sb[offB[3]] = pb1.w;
    }
    __syncthreads();
    for (int kb = 0; kb < NK; kb++) {
        const int buf = kb & 1;
        const bool more = (kb + 1 < NK);
        if (more) {
            int kofs = (kb + 1) * 16;
            int gr0 = mBase + rA, gr1 = gr0 + 64;
            pa0 = (gr0 < M) ? *(const uint4*)(A + (size_t)gr0 * K + kofs + cA) : z4;
            pa1 = (gr1 < M) ? *(const uint4*)(A + (size_t)gr1 * K + kofs + cA) : z4;
            pb0 = *(const uint4*)(W + (size_t)(kofs + rB)     * N + nBase + cB);
            pb1 = *(const uint4*)(W + (size_t)(kofs + rB + 8) * N + nBase + cB);
        }
        const uint32_t* curA = As[buf];
        const uint32_t* curB = Bs[buf];
        #pragma unroll
        for (int ks = 0; ks < 2; ks++) {
            uint4 a[4]; uint2 b[4];
            #pragma unroll
            for (int mt = 0; mt < 4; mt++) {
                int mt_g = wm * 4 + mt;
                a[mt] = *(const uint4*)&curA[((mt_g * 2 + ks) * 32 + laneA) * 4];
            }
            #pragma unroll
            for (int nt = 0; nt < 4; nt++) {
                int nt_g = wn * 4 + nt;
                b[nt] = *(const uint2*)&curB[((nt_g * 2 + ks) * 32 + (lane ^ nt_g)) * 2];
            }
            #pragma unroll
            for (int mt = 0; mt < 4; mt++)
                #pragma unroll
                for (int nt = 0; nt < 4; nt++)
                    mma_tf32(acc[mt][nt], a[mt].x, a[mt].z, a[mt].y, a[mt].w,
                             b[nt].x, b[nt].y);
        }
        if (more) {
            uint32_t* sa = As[buf ^ 1];
            sa[offA[0]] = pa0.x; sa[offA[1]] = pa0.y; sa[offA[2]] = pa0.z; sa[offA[3]] = pa0.w;
            sa += 1024;
            sa[offA[0]] = pa1.x; sa[offA[1]] = pa1.y; sa[offA[2]] = pa1.z; sa[offA[3]] = pa1.w;
            uint32_t* sb = Bs[buf ^ 1];
            sb[offB[0]] = pb0.x; sb[offB[1]] = pb0.y; sb[offB[2]] = pb0.z; sb[offB[3]] = pb0.w;
            sb += 64;
            sb[offB[0]] = pb1.x; sb[offB[1]] = pb1.y; sb[offB[2]] = pb1.z; sb[offB[3]] = pb1.w;
        }
        __syncthreads();
    }
    #pragma unroll
    for (int mt = 0; mt < 4; mt++) {
        int r0 = mBase + wm * 64 + mt * 16 + lr;
        #pragma unroll
        for (int nt = 0; nt < 4; nt++) {
            int col = nBase + wn * 32 + nt * 8 + lc * 2;
            float2 bv = *(const float2*)(bias + col);
            float* cc = acc[mt][nt];
            #pragma unroll
            for (int half = 0; half < 2; half++) {
                int r = r0 + half * 8;
                if (r >= M) continue;
                float* Cf = (float*)p.out[blockIdx.z];
                *(float2*)(Cf + (size_t)r * N + col) =
                    make_float2(cc[half * 2 + 0] + bv.x, cc[half * 2 + 1] + bv.y);
            }
        }
    }
}

// ---------------- BF16 GEMM (m16n8k16), word = bf16 k-pair ----------------
template<int EPI>
__global__ __launch_bounds__(256)
void gemm_bf16(const uint32_t* __restrict__ A, GemmPtrs p,
               int M, int N, int K, int Kloop) {
    __shared__ __align__(16) uint32_t As[2][2048];
    __shared__ __align__(16) uint32_t Bs[2][2048];
    const uint32_t* __restrict__ W    = p.W[blockIdx.z];
    const float* __restrict__    bias = p.bias[blockIdx.z];
    const int AKw  = K >> 1;
    const int aOffW = (EPI == 3) ? blockIdx.z * (Kloop >> 1) : 0;
    const int t = threadIdx.x;
    const int lane = t & 31, wid = t >> 5;
    const int wm = wid & 1, wn = wid >> 1;
    const int mBase = blockIdx.x * 128;
    const int nBase = blockIdx.y * 128;
    const int lr = lane >> 2, lc = lane & 3;
    const int rA = t >> 2,  cA = (t & 3) * 4;
    const int rB = t >> 5,  cB = (t & 31) * 4;
    const int laneA = lane ^ ((lane >> 3) & 3);
    int offA[4], offB[4];
    {
        int mt = rA >> 4, s1 = (rA >> 3) & 1, lr0 = rA & 7;
        int ks = cA >> 3, s2 = (cA >> 2) & 1;
        int e  = s1 * 2 + s2;
        int blk = (mt * 2 + ks) * 32;
        #pragma unroll
        for (int j = 0; j < 4; j++) {
            int la = 4 * lr0 + j;
            la ^= (la >> 3) & 3;
            offA[j] = (blk + la) * 4 + e;
        }
        int sB = (rB >> 2) & 1, lcb = rB & 3;
        #pragma unroll
        for (int j = 0; j < 4; j++) {
            int nn = cB + j;
            int nt = nn >> 3, lrb = nn & 7;
            int lb = (4 * lrb + lcb) ^ nt;
            offB[j] = (nt * 2 * 32 + lb) * 2 + sB;
        }
    }
    float acc[4][4][4];
    #pragma unroll
    for (int i = 0; i < 4; i++)
        #pragma unroll
        for (int j = 0; j < 4; j++)
            #pragma unroll
            for (int r = 0; r < 4; r++) acc[i][j][r] = 0.0f;
    const int NK = Kloop >> 5;
    uint4 pa0, pa1, pb0, pb1;
    const uint4 z4 = make_uint4(0u, 0u, 0u, 0u);
    {
        int gr0 = mBase + rA, gr1 = gr0 + 64;
        pa0 = (gr0 < M) ? *(const uint4*)(A + (size_t)gr0 * AKw + aOffW + cA) : z4;
        pa1 = (gr1 < M) ? *(const uint4*)(A + (size_t)gr1 * AKw + aOffW + cA) : z4;
        pb0 = *(const uint4*)(W + (size_t)rB       * N + nBase + cB);
        pb1 = *(const uint4*)(W + (size_t)(rB + 8) * N + nBase + cB);
        uint32_t* sa = As[0];
        sa[offA[0]] = pa0.x; sa[offA[1]] = pa0.y; sa[offA[2]] = pa0.z; sa[offA[3]] = pa0.w;
        sa += 1024;
        sa[offA[0]] = pa1.x; sa[offA[1]] = pa1.y; sa[offA[2]] = pa1.z; sa[offA[3]] = pa1.w;
        uint32_t* sb = Bs[0];
        sb[offB[0]] = pb0.x; sb[offB[1]] = pb0.y; sb[offB[2]] = pb0.z; sb[offB[3]] = pb0.w;
        sb += 64;
        sb[offB[0]] = pb1.x; sb[offB[1]] = pb1.y; sb[offB[2]] = pb1.z; sb[offB[3]] = pb1.w;
    }
    __syncthreads();
    for (int kb = 0; kb < NK; kb++) {
        const int buf = kb & 1;
        const bool more = (kb + 1 < NK);
        if (more) {
            int kofsW = (kb + 1) * 16;
            int gr0 = mBase + rA, gr1 = gr0 + 64;
            pa0 = (gr0 < M) ? *(const uint4*)(A + (size_t)gr0 * AKw + aOffW + kofsW + cA) : z4;
            pa1 = (gr1 < M) ? *(const uint4*)(A + (size_t)gr1 * AKw + aOffW + kofsW + cA) : z4;
            pb0 = *(const uint4*)(W + (size_t)(kofsW + rB)     * N + nBase + cB);
            pb1 = *(const uint4*)(W + (size_t)(kofsW + rB + 8) * N + nBase + cB);
        }
        const uint32_t* curA = As[buf];
        const uint32_t* curB = Bs[buf];
        #pragma unroll
        for (int ks = 0; ks < 2; ks++) {
            uint4 a[4]; uint2 b[4];
            #pragma unroll
            for (int mt = 0; mt < 4; mt++) {
                int mt_g = wm * 4 + mt;
                a[mt] = *(const uint4*)&curA[((mt_g * 2 + ks) * 32 + laneA) * 4];
            }
            #pragma unroll
            for (int nt = 0; nt < 4; nt++) {
                int nt_g = wn * 4 + nt;
                b[nt] = *(const uint2*)&curB[((nt_g * 2 + ks) * 32 + (lane ^ nt_g)) * 2];
            }
            #pragma unroll
            for (int mt = 0; mt < 4; mt++)
                #pragma unroll
                for (int nt = 0; nt < 4; nt++)
                    mma_bf16(acc[mt][nt], a[mt].x, a[mt].z, a[mt].y, a[mt].w,
                             b[nt].x, b[nt].y);
        }
        if (more) {
            uint32_t* sa = As[buf ^ 1];
            sa[offA[0]] = pa0.x; sa[offA[1]] = pa0.y; sa[offA[2]] = pa0.z; sa[offA[3]] = pa0.w;
            sa += 1024;
            sa[offA[0]] = pa1.x; sa[offA[1]] = pa1.y; sa[offA[2]] = pa1.z; sa[offA[3]] = pa1.w;
            uint32_t* sb = Bs[buf ^ 1];
            sb[offB[0]] = pb0.x; sb[offB[1]] = pb0.y; sb[offB[2]] = pb0.z; sb[offB[3]] = pb0.w;
            sb += 64;
            sb[offB[0]] = pb1.x; sb[offB[1]] = pb1.y; sb[offB[2]] = pb1.z; sb[offB[3]] = pb1.w;
        }
        __syncthreads();
    }
    #pragma unroll
    for (int mt = 0; mt < 4; mt++) {
        int r0 = mBase + wm * 64 + mt * 16 + lr;
        #pragma unroll
        for (int nt = 0; nt < 4; nt++) {
            int col = nBase + wn * 32 + nt * 8 + lc * 2;
            float2 bv = make_float2(0.f, 0.f);
            if (EPI != 3) bv = *(const float2*)(bias + col);
            float* cc = acc[mt][nt];
            #pragma unroll
            for (int half = 0; half < 2; half++) {
                int r = r0 + half * 8;
                if (r >= M) continue;
                float ox = cc[half * 2 + 0] + bv.x;
                float oy = cc[half * 2 + 1] + bv.y;
                if (EPI == 3) {
                    float* Cf = (float*)p.out[0];
                    red_add_v2(Cf + (size_t)r * N + col, ox, oy);
                } else {
                    if (EPI == 5) { ox = gelu_exact(ox); oy = gelu_exact(oy); }
                    __nv_bfloat16* Cb = (__nv_bfloat16*)p.out[blockIdx.z];
                    *(uint32_t*)(Cb + (size_t)r * N + col) = pack_bf2(ox, oy);
                }
            }
        }
    }
}

// ---------------- CSR aggregation over dst range [dst0, dst0+nrows) ----------------
__global__ void agg_csr_kernel(const int* __restrict__ csrsrc,
                               const int* __restrict__ rowptr,
                               const __nv_bfloat16* __restrict__ q,
                               const __nv_bfloat16* __restrict__ k,
                               const __nv_bfloat16* __restrict__ v,
                               float* __restrict__ den, float* __restrict__ agg,
                               int dst0, int nrows) {
    int r = (blockIdx.x * blockDim.x + threadIdx.x) >> 5;
    if (r >= nrows) return;
    int dst = dst0 + r;
    int lane = threadIdx.x & 31;
    uint4 qv = ((const uint4*)(q + (size_t)dst * HID))[lane];
    float qf[8];
    {
        const __nv_bfloat162* qh = (const __nv_bfloat162*)&qv;
        #pragma unroll
        for (int i = 0; i < 4; i++) {
            float2 f = __bfloat1622float2(qh[i]);
            qf[2 * i] = f.x; qf[2 * i + 1] = f.y;
        }
    }
    float acc[8] = {0.f, 0.f, 0.f, 0.f, 0.f, 0.f, 0.f, 0.f};
    float densum = 0.0f;
    int beg = rowptr[dst], endi = rowptr[dst + 1];
    for (int i = beg; i < endi; i++) {
        int src = csrsrc[i];
        uint4 kv = ((const uint4*)(k + (size_t)src * HID))[lane];
        uint4 vv = ((const uint4*)(v + (size_t)src * HID))[lane];
        float d = 0.f;
        const __nv_bfloat162* kh = (const __nv_bfloat162*)&kv;
        #pragma unroll
        for (int j = 0; j < 4; j++) {
            float2 f = __bfloat1622float2(kh[j]);
            d += qf[2 * j] * f.x + qf[2 * j + 1] * f.y;
        }
        d += __shfl_xor_sync(0xffffffffu, d, 1);
        d += __shfl_xor_sync(0xffffffffu, d, 2);
        d += __shfl_xor_sync(0xffffffffu, d, 4);
        float w = __expf(d * 0.125f);
        densum += w;
        const __nv_bfloat162* vh = (const __nv_bfloat162*)&vv;
        #pragma unroll
        for (int j = 0; j < 4; j++) {
            float2 f = __bfloat1622float2(vh[j]);
            acc[2 * j]     += w * f.x;
            acc[2 * j + 1] += w * f.y;
        }
    }
    float* op = agg + (size_t)dst * HID + lane * 8;
    *(float4*)op       = make_float4(acc[0], acc[1], acc[2], acc[3]);
    *(float4*)(op + 4) = make_float4(acc[4], acc[5], acc[6], acc[7]);
    if ((lane & 7) == 0) den[dst * NHEAD + (lane >> 3)] = densum;
}

// ---------------- host launch ----------------
extern "C" void kernel_launch(void* const* d_in, const int* in_sizes, int n_in,
                              void* d_out, int out_size) {
    const float* x     = (const float*)d_in[0];
    const int*   ei    = (const int*)d_in[1];
    const float* ln1_w = (const float*)d_in[2];
    const float* ln1_b = (const float*)d_in[3];
    const float* ln2_w = (const float*)d_in[4];
    const float* ln2_b = (const float*)d_in[5];
    const float* wq    = (const float*)d_in[6];
    const float* bq    = (const float*)d_in[7];
    const float* wk    = (const float*)d_in[8];
    const float* bk    = (const float*)d_in[9];
    const float* wv    = (const float*)d_in[10];
    const float* bv    = (const float*)d_in[11];
    const float* wskip = (const float*)d_in[12];
    const float* bskip = (const float*)d_in[13];
    const float* w1    = (const float*)d_in[14];
    const float* b1    = (const float*)d_in[15];
    const float* w2    = (const float*)d_in[16];
    const float* b2    = (const float*)d_in[17];

    int n = in_sizes[0] / HID;
    int E = in_sizes[1] / 2;
    int nlo = 10112 < n ? 10112 : n;     // 79 tiles of 128
    int nhi = n - nlo;

    static uint32_t *h = nullptr, *h16, *wt0, *wt1, *wt2, *wt3, *w1t, *w2t;
    static __nv_bfloat16 *q, *k, *v, *mid;
    static float *skip, *agg, *den;
    static int *cnt, *rowptr, *wpos, *csrsrc;
    static cudaStream_t s2;
    static cudaEvent_t ev0, evA, evB, evC, evD, evS, evQ, evF;
    if (!h) {
        cudaGetSymbolAddress((void**)&h,      g_h);
        cudaGetSymbolAddress((void**)&h16,    g_h16);
        cudaGetSymbolAddress((void**)&q,      g_q);
        cudaGetSymbolAddress((void**)&k,      g_k);
        cudaGetSymbolAddress((void**)&v,      g_v);
        cudaGetSymbolAddress((void**)&skip,   g_skip);
        cudaGetSymbolAddress((void**)&agg,    g_agg);
        cudaGetSymbolAddress((void**)&mid,    g_mid);
        cudaGetSymbolAddress((void**)&den,    g_den);
        cudaGetSymbolAddress((void**)&cnt,    g_count);
        cudaGetSymbolAddress((void**)&rowptr, g_rowptr);
        cudaGetSymbolAddress((void**)&wpos,   g_wpos);
        cudaGetSymbolAddress((void**)&csrsrc, g_csrsrc);
        cudaGetSymbolAddress((void**)&wt0,    g_wt);
        wt1 = wt0 + HID * HID; wt2 = wt1 + HID * HID; wt3 = wt2 + HID * HID;
        cudaGetSymbolAddress((void**)&w1t,    g_w1t);
        cudaGetSymbolAddress((void**)&w2t,    g_w2t);
        cudaStreamCreateWithFlags(&s2, cudaStreamNonBlocking);
        cudaEventCreateWithFlags(&ev0, cudaEventDisableTiming);
        cudaEventCreateWithFlags(&evA, cudaEventDisableTiming);
        cudaEventCreateWithFlags(&evB, cudaEventDisableTiming);
        cudaEventCreateWithFlags(&evC, cudaEventDisableTiming);
        cudaEventCreateWithFlags(&evD, cudaEventDisableTiming);
        cudaEventCreateWithFlags(&evS, cudaEventDisableTiming);
        cudaEventCreateWithFlags(&evQ, cudaEventDisableTiming);
        cudaEventCreateWithFlags(&evF, cudaEventDisableTiming);
    }

    // Legal capture fork: s2's first node waits on an event from the capture stream.
    cudaEventRecord(ev0, 0);
    cudaStreamWaitEvent(s2, ev0, 0);

    // s2: weight conversions
    {
        WPack wp;
        wp.src[0] = wq; wp.dst[0] = wt0;
        wp.src[1] = wk; wp.dst[1] = wt1;
        wp.src[2] = wv; wp.dst[2] = wt2;
        wp.src[3] = w1; wp.dst[3] = w1t;
        wp.src[4] = w2; wp.dst[4] = w2t;
        cvt_bf16pack_kernel<<<224, 256, 0, s2>>>(wp);
        cvt_wskip_kernel<<<64, 256, 0, s2>>>(wskip, wt3);
    }
    cudaEventRecord(evC, s2);                      // weights ready

    // main: zero degree counters, detect dtype (fast)
    init_kernel<<<(n + 255) / 256, 256>>>(cnt, n);
    detect_kernel<<<1, 32>>>(ei, E);
    cudaEventRecord(evD, 0);

    // s2: CSR build
    cudaStreamWaitEvent(s2, evD, 0);
    count_kernel<<<(E + 255) / 256, 256, 0, s2>>>(ei, cnt, E);
    scan_kernel<<<1, SCAN_T, 0, s2>>>(cnt, rowptr, wpos, n);
    scatter_kernel<<<(E + 255) / 256, 256, 0, s2>>>(ei, wpos, csrsrc, E);

    ln_kernel<<<(n * 32 + 255) / 256, 256>>>(x, ln1_w, ln1_b, h, h16, n);
    cudaEventRecord(evA, 0);                       // h ready

    // s2: skip projection
    cudaStreamWaitEvent(s2, evA, 0);
    {
        GemmPtrs p;
        p.W[0] = wt3; p.bias[0] = bskip; p.out[0] = skip;
        dim3 g((n + 127) / 128, HID / 128, 1);
        gemm_tf32<0><<<g, 256, 0, s2>>>(h, p, n, HID, HID, HID);
    }
    cudaEventRecord(evS, s2);                      // CSR + skip ready (s2 in-order)

    cudaStreamWaitEvent(0, evC, 0);                // main: weights ready
    {
        GemmPtrs p;
        p.W[0] = wt0; p.bias[0] = bq; p.out[0] = q;
        p.W[1] = wt1; p.bias[1] = bk; p.out[1] = k;
        p.W[2] = wt2; p.bias[2] = bv; p.out[2] = v;
        dim3 g((n + 127) / 128, HID / 128, 3);
        gemm_bf16<4><<<g, 256>>>(h16, p, n, HID, HID, HID);
    }
    cudaEventRecord(evQ, 0);                       // q/k/v ready

    // ---- two independent row chains: lo on main, hi on s2 ----
    cudaStreamWaitEvent(0, evS, 0);                // main: CSR + skip
    cudaStreamWaitEvent(s2, evQ, 0);               // s2: q/k/v

    // lo chain (main)
    agg_csr_kernel<<<(nlo * 32 + 255) / 256, 256>>>(csrsrc, rowptr, q, k, v, den, agg, 0, nlo);
    add_ln_kernel<<<(nlo * 32 + 255) / 256, 256>>>(x, skip, agg, den, ln2_w, ln2_b, b2,
                                                   (float*)d_out, h16, 0, nlo);
    {
        GemmPtrs p;
        p.W[0] = w1t; p.bias[0] = b1; p.out[0] = mid;
        dim3 g((nlo + 127) / 128, (2 * HID) / 128, 1);
        gemm_bf16<5><<<g, 256>>>(h16, p, nlo, 2 * HID, HID, HID);
    }
    {
        GemmPtrs p;
        p.W[0] = w2t;             p.bias[0] = b2; p.out[0] = d_out;
        p.W[1] = w2t + 128 * HID; p.bias[1] = b2; p.out[1] = d_out;
        dim3 g((nlo + 127) / 128, HID / 128, 2);
        gemm_bf16<3><<<g, 256>>>((const uint32_t*)mid, p, nlo, HID, 2 * HID, HID);
    }

    // hi chain (s2)
    if (nhi > 0) {
        agg_csr_kernel<<<(nhi * 32 + 255) / 256, 256, 0, s2>>>(csrsrc, rowptr, q, k, v,
                                                               den, agg, nlo, nhi);
        add_ln_kernel<<<(nhi * 32 + 255) / 256, 256, 0, s2>>>(x, skip, agg, den,
                                                              ln2_w, ln2_b, b2,
                                                              (float*)d_out, h16, nlo, nhi);
        {
            GemmPtrs p;
            p.W[0] = w1t; p.bias[0] = b1;
            p.out[0] = mid + (size_t)nlo * 2 * HID;
            dim3 g((nhi + 127) / 128, (2 * HID) / 128, 1);
            gemm_bf16<5><<<g, 256, 0, s2>>>(h16 + (size_t)nlo * (HID / 2), p,
                                            nhi, 2 * HID, HID, HID);
        }
        {
            GemmPtrs p;
            p.W[0] = w2t;             p.bias[0] = b2;
            p.W[1] = w2t + 128 * HID; p.bias[1] = b2;
            p.out[0] = (float*)d_out + (size_t)nlo * HID;
            p.out[1] = (float*)d_out + (size_t)nlo * HID;
            dim3 g((nhi + 127) / 128, HID / 128, 2);
            gemm_bf16<3><<<g, 256, 0, s2>>>((const uint32_t*)(mid + (size_t)nlo * 2 * HID), p,
                                            nhi, HID, 2 * HID, HID);
        }
    }
    cudaEventRecord(evF, s2);
    cudaStreamWaitEvent(0, evF, 0);                // join s2 back into capture stream
}